// round 8
// baseline (speedup 1.0000x reference)
#include <cuda_runtime.h>
#include <math.h>

// Problem constants: B=16, T=128 -> 2048 graphs; J=75 nodes;
// D_IN=3, HID=64, OUT=256; E=300 edges (derived from in_sizes at launch).
#define NJ    75
#define DIN   3
#define HID   64
#define NOUT  256
#define MAX_E 1024
#define MAX_T 544

typedef unsigned long long u64;

__device__ int   g_csr_src[MAX_T];
__device__ float g_csr_w[MAX_T];
__device__ int   g_csr_off[NJ + 1];

// ---- packed f32x2 helpers (sm_103a FFMA2, PTX-only path) ----
__device__ __forceinline__ u64 pack2(float lo, float hi) {
    u64 r; asm("mov.b64 %0, {%1, %2};" : "=l"(r) : "f"(lo), "f"(hi)); return r;
}
__device__ __forceinline__ void fma2(u64& d, u64 a, u64 b) {
    asm("fma.rn.f32x2 %0, %1, %2, %0;" : "+l"(d) : "l"(a), "l"(b));
}
__device__ __forceinline__ float2 unpack2(u64 v) {
    float2 r; asm("mov.b64 {%0, %1}, %2;" : "=f"(r.x), "=f"(r.y) : "l"(v)); return r;
}

// Branchless gelu: 0.5*v*(1+erf(v/sqrt2)), erf via Abramowitz-Stegun 7.1.26
// (|abs err| <= 1.5e-7, far inside the 1e-3 harness tolerance).
__device__ __forceinline__ float gelu_fast(float v) {
    const float x  = v * 0.70710678118654752f;
    const float ax = fabsf(x);
    const float den = fmaf(0.3275911f, ax, 1.0f);
    const float t   = __frcp_rn(den);
    float p = fmaf(1.061405429f, t, -1.453152027f);
    p = fmaf(p, t, 1.421413741f);
    p = fmaf(p, t, -0.284496736f);
    p = fmaf(p, t, 0.254829592f);
    p = p * t;
    const float ex   = __expf(-x * x);
    const float erfa = fmaf(-p, ex, 1.0f);      // erf(|x|)
    const float erfv = copysignf(erfa, x);
    return 0.5f * v * (1.0f + erfv);
}

__device__ __forceinline__ int clampj(int v) {
    return v < 0 ? 0 : (v >= NJ ? NJ - 1 : v);
}

// ---------------------------------------------------------------------------
// Build CSR (per-dst in-edge lists incl. self-loops) from edge_index (2,E).
// Dtype-agnostic (int32 vs int64 detection via odd-word scan).
// ---------------------------------------------------------------------------
__global__ void setup_csr(const void* __restrict__ eiv, int E) {
    const int*       e32 = (const int*)eiv;
    const long long* e64 = (const long long*)eiv;

    __shared__ int   s_is64;
    __shared__ int   s_src[MAX_E];
    __shared__ int   s_dst[MAX_E];
    __shared__ int   s_deg[NJ];
    __shared__ float s_dis[NJ];
    __shared__ int   s_off[NJ + 1];

    int t = threadIdx.x;

    if (t == 0) {
        int odd_nonzero = 0;
        for (int i = 1; i < 2 * E; i += 2) odd_nonzero |= (e32[i] != 0);
        s_is64 = !odd_nonzero;
    }
    __syncthreads();
    const int is64 = s_is64;

    for (int i = t; i < E; i += blockDim.x) {
        int sv, dv;
        if (is64) { sv = (int)e64[i]; dv = (int)e64[E + i]; }
        else      { sv = e32[i];      dv = e32[E + i]; }
        s_src[i] = clampj(sv);
        s_dst[i] = clampj(dv);
    }
    for (int j = t; j < NJ; j += blockDim.x) s_deg[j] = 1;  // self loop
    __syncthreads();
    for (int i = t; i < E; i += blockDim.x) atomicAdd(&s_deg[s_dst[i]], 1);
    __syncthreads();
    if (t == 0) {
        int acc = 0;
        for (int j = 0; j < NJ; j++) { s_off[j] = acc; acc += s_deg[j]; }
        s_off[NJ] = acc;
    }
    for (int j = t; j < NJ; j += blockDim.x) s_dis[j] = rsqrtf((float)s_deg[j]);
    __syncthreads();
    if (t < NJ) {
        int p = s_off[t];
        float dj = s_dis[t];
        for (int e = 0; e < E; e++) {
            if (s_dst[e] == t) {
                int se = s_src[e];
                g_csr_src[p] = se;
                g_csr_w[p]   = s_dis[se] * dj;
                p++;
            }
        }
        g_csr_src[p] = t;        // self loop last
        g_csr_w[p]   = dj * dj;
    }
    for (int j = t; j <= NJ; j += blockDim.x) g_csr_off[j] = s_off[j];
}

// ---------------------------------------------------------------------------
// Fully fused per-graph GCN:
//   out = gelu( A * gelu( (A*x) W1 + b1 ) * W2 + b2 )
// One CTA per graph; 256 threads; intermediates in SMEM.
// ---------------------------------------------------------------------------
__global__ void __launch_bounds__(256)
gcn_fused(const float* __restrict__ x,
          const float* __restrict__ W1, const float* __restrict__ b1,
          const float* __restrict__ W2, const float* __restrict__ b2,
          float* __restrict__ out, int nTot) {
    __shared__ __align__(16) float s_x  [NJ * DIN];
    __shared__ __align__(16) float s_ax [NJ * DIN];
    __shared__ __align__(16) float s_h1 [NJ * HID];
    __shared__ __align__(16) float s_ah1[NJ * HID];
    __shared__ __align__(16) float s_W1 [DIN * HID];
    __shared__ __align__(16) float s_b1 [HID];
    __shared__ __align__(16) float s_b2 [NOUT];
    __shared__ int   s_off[NJ + 1];
    __shared__ int   s_src[MAX_T];
    __shared__ __align__(16) float s_w[MAX_T];

    const int t = threadIdx.x;
    const int g = blockIdx.x;

    // ---- cooperative loads ----
    const float* xg = x + (size_t)g * (NJ * DIN);
    for (int i = t; i < NJ * DIN; i += 256) s_x[i] = xg[i];
    for (int i = t; i < DIN * HID; i += 256) s_W1[i] = W1[i];
    if (t < HID) s_b1[t] = b1[t];
    s_b2[t] = b2[t];
    for (int i = t; i <= NJ; i += 256) s_off[i] = g_csr_off[i];
    for (int i = t; i < nTot; i += 256) { s_src[i] = g_csr_src[i]; s_w[i] = g_csr_w[i]; }

    // W2 column for this thread's channel, packed as 32 f32x2 pairs
    // (coalesced LDG, overlaps the sync below).
    u64 w2c2[32];
#pragma unroll
    for (int p = 0; p < 32; p++)
        w2c2[p] = pack2(W2[(2 * p) * NOUT + t], W2[(2 * p + 1) * NOUT + t]);

    __syncthreads();

    // ---- phase 1: ax = A * x  (J*3 = 225 outputs) ----
    for (int idx = t; idx < NJ * DIN; idx += 256) {
        int j = idx / DIN, d = idx - j * DIN;
        float acc = 0.f;
        int e0 = s_off[j], e1 = s_off[j + 1];
        for (int e = e0; e < e1; e++) acc += s_w[e] * s_x[s_src[e] * DIN + d];
        s_ax[idx] = acc;
    }
    __syncthreads();

    // ---- phase 2: h1 = gelu(ax @ W1 + b1) ----
    for (int idx = t; idx < NJ * HID; idx += 256) {
        int j = idx >> 6, k = idx & 63;
        float a0 = s_ax[j * DIN + 0];
        float a1 = s_ax[j * DIN + 1];
        float a2 = s_ax[j * DIN + 2];
        float v = fmaf(a0, s_W1[k],
                  fmaf(a1, s_W1[HID + k],
                  fmaf(a2, s_W1[2 * HID + k], s_b1[k])));
        s_h1[idx] = gelu_fast(v);
    }
    __syncthreads();

    // ---- phase 3: ah1 = A * h1 ----
    for (int idx = t; idx < NJ * HID; idx += 256) {
        int j = idx >> 6, k = idx & 63;
        float acc = 0.f;
        int e0 = s_off[j], e1 = s_off[j + 1];
        for (int e = e0; e < e1; e++) acc += s_w[e] * s_h1[(s_src[e] << 6) + k];
        s_ah1[idx] = acc;
    }
    __syncthreads();

    // ---- phase 4: out = gelu(ah1 @ W2 + b2), FFMA2-packed, coalesced store ----
    const float bc = s_b2[t];
    float* og = out + (size_t)g * (NJ * NOUT) + t;

    for (int j = 0; j < NJ; j++) {
        const ulonglong2* row = (const ulonglong2*)(s_ah1 + j * HID);  // 16 x LDS.128
        u64 acc0 = 0ull, acc1 = 0ull;   // two packed {+0,+0} accumulators
#pragma unroll
        for (int p = 0; p < 16; p++) {
            ulonglong2 v = row[p];       // floats 4p..4p+3
            fma2(acc0, v.x, w2c2[2 * p]);
            fma2(acc1, v.y, w2c2[2 * p + 1]);
        }
        float2 a0 = unpack2(acc0);
        float2 a1 = unpack2(acc1);
        float acc = bc + ((a0.x + a1.x) + (a0.y + a1.y));
        og[(size_t)j * NOUT] = gelu_fast(acc);
    }
}

// ---------------------------------------------------------------------------
extern "C" void kernel_launch(void* const* d_in, const int* in_sizes, int n_in,
                              void* d_out, int out_size) {
    const float* x  = (const float*)d_in[0];
    const void*  ei = d_in[1];                     // int32 or int64 (2, E)
    const float* W1 = (const float*)d_in[2];
    const float* b1 = (const float*)d_in[3];
    const float* W2 = (const float*)d_in[4];
    const float* b2 = (const float*)d_in[5];
    float* out = (float*)d_out;

    const int E  = in_sizes[1] / 2;                // 300
    const int nG = in_sizes[0] / (NJ * DIN);       // 2048 graphs
    const int nTot = E + NJ;                       // CSR entries

    setup_csr<<<1, 128>>>(ei, E);
    gcn_fused<<<nG, 256>>>(x, W1, b1, W2, b2, out, nTot);
}

// round 10
// speedup vs baseline: 2.0937x; 2.0937x over previous
#include <cuda_runtime.h>
#include <cuda_bf16.h>
#include <math.h>
#include <stdint.h>

// Problem constants: B=16,T=128 -> 2048 graphs; J=75; 3->64->256; E=300.
#define NJ    75
#define DIN   3
#define HID   64
#define NOUT  256
#define MAX_E 1024
#define MAX_T 544
#define MAXG  2048

// ---------------- persistent device scratch ----------------
__device__ int   g_csr_src[MAX_T];
__device__ float g_csr_w[MAX_T];
__device__ int   g_csr_off[NJ + 1];
__device__ __nv_bfloat16 g_ah_hi[MAXG * NJ * HID];   // ah1 split hi [row][k]
__device__ __nv_bfloat16 g_ah_lo[MAXG * NJ * HID];   // ah1 split lo
__device__ __nv_bfloat16 g_w2t_hi[NOUT * HID];       // W2^T split hi [n][k]
__device__ __nv_bfloat16 g_w2t_lo[NOUT * HID];       // W2^T split lo

// ---------------- math helpers ----------------
__device__ __forceinline__ float gelu_fast(float v) {
    const float x  = v * 0.70710678118654752f;
    const float ax = fabsf(x);
    const float den = fmaf(0.3275911f, ax, 1.0f);
    const float t   = __frcp_rn(den);
    float p = fmaf(1.061405429f, t, -1.453152027f);
    p = fmaf(p, t, 1.421413741f);
    p = fmaf(p, t, -0.284496736f);
    p = fmaf(p, t, 0.254829592f);
    p = p * t;
    const float ex   = __expf(-x * x);
    const float erfa = fmaf(-p, ex, 1.0f);
    return 0.5f * v * (1.0f + copysignf(erfa, x));
}
__device__ __forceinline__ int clampj(int v) {
    return v < 0 ? 0 : (v >= NJ ? NJ - 1 : v);
}

// Classic warp-level bf16 MMA (sm_80+ PTX, legal on plain sm_103 target).
// D(16x8,f32) += A(16x16,bf16 row) * B(16x8,bf16 col)
#define MMA_BF16(d, a0, a1, a2, a3, b0, b1)                                   \
    asm volatile("mma.sync.aligned.m16n8k16.row.col.f32.bf16.bf16.f32 "       \
        "{%0,%1,%2,%3}, {%4,%5,%6,%7}, {%8,%9}, {%0,%1,%2,%3};"               \
        : "+f"((d)[0]), "+f"((d)[1]), "+f"((d)[2]), "+f"((d)[3])              \
        : "r"(a0), "r"(a1), "r"(a2), "r"(a3), "r"(b0), "r"(b1))

// ---------------------------------------------------------------------------
// Setup: CSR of normalized adjacency + W2^T bf16 hi/lo split. One block.
// ---------------------------------------------------------------------------
__global__ void setup_csr(const void* __restrict__ eiv, int E,
                          const float* __restrict__ W2) {
    const int*       e32 = (const int*)eiv;
    const long long* e64 = (const long long*)eiv;

    __shared__ int   s_is64;
    __shared__ int   s_src[MAX_E];
    __shared__ int   s_dst[MAX_E];
    __shared__ int   s_deg[NJ];
    __shared__ float s_dis[NJ];
    __shared__ int   s_off[NJ + 1];

    int t = threadIdx.x;

    // W2^T hi/lo split
    for (int i = t; i < NOUT * HID; i += blockDim.x) {
        int n = i & (NOUT - 1), k = i >> 8;
        float f = W2[k * NOUT + n];
        __nv_bfloat16 h = __float2bfloat16(f);
        __nv_bfloat16 l = __float2bfloat16(f - __bfloat162float(h));
        g_w2t_hi[n * HID + k] = h;
        g_w2t_lo[n * HID + k] = l;
    }

    if (t == 0) {
        int odd_nonzero = 0;
        for (int i = 1; i < 2 * E; i += 2) odd_nonzero |= (e32[i] != 0);
        s_is64 = !odd_nonzero;
    }
    __syncthreads();
    const int is64 = s_is64;

    for (int i = t; i < E; i += blockDim.x) {
        int sv, dv;
        if (is64) { sv = (int)e64[i]; dv = (int)e64[E + i]; }
        else      { sv = e32[i];      dv = e32[E + i]; }
        s_src[i] = clampj(sv);
        s_dst[i] = clampj(dv);
    }
    for (int j = t; j < NJ; j += blockDim.x) s_deg[j] = 1;  // self loop
    __syncthreads();
    for (int i = t; i < E; i += blockDim.x) atomicAdd(&s_deg[s_dst[i]], 1);
    __syncthreads();
    if (t == 0) {
        int acc = 0;
        for (int j = 0; j < NJ; j++) { s_off[j] = acc; acc += s_deg[j]; }
        s_off[NJ] = acc;
    }
    for (int j = t; j < NJ; j += blockDim.x) s_dis[j] = rsqrtf((float)s_deg[j]);
    __syncthreads();
    if (t < NJ) {
        int p = s_off[t];
        float dj = s_dis[t];
        for (int e = 0; e < E; e++) {
            if (s_dst[e] == t) {
                int se = s_src[e];
                g_csr_src[p] = se;
                g_csr_w[p]   = s_dis[se] * dj;
                p++;
            }
        }
        g_csr_src[p] = t;
        g_csr_w[p]   = dj * dj;
    }
    for (int j = t; j <= NJ; j += blockDim.x) g_csr_off[j] = s_off[j];
}

// ---------------------------------------------------------------------------
// Part A (per-graph CTA): ah1 = A * gelu((A*x) W1 + b1), split to bf16 hi/lo.
// (Measured ~25us incl. global writes in round 8.)
// ---------------------------------------------------------------------------
__global__ void __launch_bounds__(256)
gcn_partA(const float* __restrict__ x,
          const float* __restrict__ W1, const float* __restrict__ b1,
          int nTot) {
    __shared__ __align__(16) float s_x  [NJ * DIN];
    __shared__ __align__(16) float s_ax [NJ * DIN];
    __shared__ __align__(16) float s_h1 [NJ * HID];
    __shared__ __align__(16) float s_ah1[NJ * HID];
    __shared__ __align__(16) float s_W1 [DIN * HID];
    __shared__ __align__(16) float s_b1 [HID];
    __shared__ int s_off[NJ + 1];
    __shared__ int s_src[MAX_T];
    __shared__ __align__(16) float s_w[MAX_T];

    const int t = threadIdx.x;
    const int g = blockIdx.x;

    const float* xg = x + (size_t)g * (NJ * DIN);
    for (int i = t; i < NJ * DIN; i += 256) s_x[i] = xg[i];
    for (int i = t; i < DIN * HID; i += 256) s_W1[i] = W1[i];
    if (t < HID) s_b1[t] = b1[t];
    for (int i = t; i <= NJ; i += 256) s_off[i] = g_csr_off[i];
    for (int i = t; i < nTot; i += 256) { s_src[i] = g_csr_src[i]; s_w[i] = g_csr_w[i]; }
    __syncthreads();

    // phase 1: ax = A * x
    for (int idx = t; idx < NJ * DIN; idx += 256) {
        int j = idx / DIN, d = idx - j * DIN;
        float acc = 0.f;
        int e0 = s_off[j], e1 = s_off[j + 1];
        for (int e = e0; e < e1; e++) acc += s_w[e] * s_x[s_src[e] * DIN + d];
        s_ax[idx] = acc;
    }
    __syncthreads();

    // phase 2: h1 = gelu(ax @ W1 + b1)
    for (int idx = t; idx < NJ * HID; idx += 256) {
        int j = idx >> 6, k = idx & 63;
        float v = fmaf(s_ax[j * DIN + 0], s_W1[k],
                  fmaf(s_ax[j * DIN + 1], s_W1[HID + k],
                  fmaf(s_ax[j * DIN + 2], s_W1[2 * HID + k], s_b1[k])));
        s_h1[idx] = gelu_fast(v);
    }
    __syncthreads();

    // phase 3: ah1 = A * h1
    for (int idx = t; idx < NJ * HID; idx += 256) {
        int j = idx >> 6, k = idx & 63;
        float acc = 0.f;
        int e0 = s_off[j], e1 = s_off[j + 1];
        for (int e = e0; e < e1; e++) acc += s_w[e] * s_h1[(s_src[e] << 6) + k];
        s_ah1[idx] = acc;
    }
    __syncthreads();

    // split to bf16 hi/lo, coalesced store
    const size_t base = (size_t)g * (NJ * HID);
    for (int i = t; i < NJ * HID; i += 256) {
        float f = s_ah1[i];
        __nv_bfloat16 h = __float2bfloat16(f);
        __nv_bfloat16 l = __float2bfloat16(f - __bfloat162float(h));
        g_ah_hi[base + i] = h;
        g_ah_lo[base + i] = l;
    }
}

// ---------------------------------------------------------------------------
// Part B: out = gelu(AH1[Mtotal,64] @ W2[64,256] + b2) via warp-level
// bf16 mma.sync with 3-term hi/lo compensation. 128-row M tiles.
//
// SMEM tiles stored as packed-bf16x2 u32 rows with stride 36 (32 k-pairs + 4
// pad) so fragment gathers hit banks (g*4 + t) -> conflict-free.
// ---------------------------------------------------------------------------
#define STRD 36
#define SM_AHI 0
#define SM_ALO (SM_AHI + 128 * STRD * 4)            // 18432
#define SM_BHI (SM_ALO + 128 * STRD * 4)            // 36864
#define SM_BLO (SM_BHI + 256 * STRD * 4)            // 73728
#define SM_B2  (SM_BLO + 256 * STRD * 4)            // 110592
#define SMB_TOTAL (SM_B2 + NOUT * 4)                // 111616

__global__ void __launch_bounds__(256)
gemm_gelu(const float* __restrict__ b2, float* __restrict__ out, int Mtotal) {
    extern __shared__ __align__(16) char smem[];
    uint32_t* sAh = (uint32_t*)(smem + SM_AHI);
    uint32_t* sAl = (uint32_t*)(smem + SM_ALO);
    uint32_t* sBh = (uint32_t*)(smem + SM_BHI);
    uint32_t* sBl = (uint32_t*)(smem + SM_BLO);
    float*    b2s = (float*)(smem + SM_B2);

    const int t   = threadIdx.x;
    const int wid = t >> 5;
    const int lid = t & 31;
    const int gq  = lid >> 2;      // fragment "group" 0..7
    const int tq  = lid & 3;       // thread-in-group 0..3
    const long r0 = (long)blockIdx.x * 128;

    // ---- load A tile (128 rows x 32 u32 pairs), clamp OOB rows ----
    for (int i = t; i < 128 * 32; i += 256) {
        int row = i >> 5, p = i & 31;
        long r = r0 + row; if (r >= Mtotal) r = Mtotal - 1;
        sAh[row * STRD + p] = ((const uint32_t*)g_ah_hi)[r * 32 + p];
        sAl[row * STRD + p] = ((const uint32_t*)g_ah_lo)[r * 32 + p];
    }
    // ---- load B tile (W2^T: 256 rows x 32 u32 pairs) ----
    for (int i = t; i < 256 * 32; i += 256) {
        int row = i >> 5, p = i & 31;
        sBh[row * STRD + p] = ((const uint32_t*)g_w2t_hi)[row * 32 + p];
        sBl[row * STRD + p] = ((const uint32_t*)g_w2t_lo)[row * 32 + p];
    }
    if (t < NOUT) b2s[t] = b2[t];
    __syncthreads();

    // ---- 8 M-tiles of 16; warp wid owns 32 output columns (4 N-tiles of 8) ----
    const int colbase = wid * 32;
    for (int m = 0; m < 8; m++) {
        float acc[4][4];
#pragma unroll
        for (int n = 0; n < 4; n++) { acc[n][0] = acc[n][1] = acc[n][2] = acc[n][3] = 0.f; }

#pragma unroll
        for (int q = 0; q < 4; q++) {
            const int ra = (m * 16 + gq) * STRD + q * 8 + tq;
            const uint32_t ah0 = sAh[ra],           ah1 = sAh[ra + 8 * STRD];
            const uint32_t ah2 = sAh[ra + 4],       ah3 = sAh[ra + 8 * STRD + 4];
            const uint32_t al0 = sAl[ra],           al1 = sAl[ra + 8 * STRD];
            const uint32_t al2 = sAl[ra + 4],       al3 = sAl[ra + 8 * STRD + 4];
#pragma unroll
            for (int n = 0; n < 4; n++) {
                const int rb = (colbase + n * 8 + gq) * STRD + q * 8 + tq;
                const uint32_t bh0 = sBh[rb], bh1 = sBh[rb + 4];
                const uint32_t bl0 = sBl[rb], bl1 = sBl[rb + 4];
                MMA_BF16(acc[n], ah0, ah1, ah2, ah3, bh0, bh1);
                MMA_BF16(acc[n], al0, al1, al2, al3, bh0, bh1);
                MMA_BF16(acc[n], ah0, ah1, ah2, ah3, bl0, bl1);
            }
        }

        // epilogue: rows r0+m*16+gq and +8; cols colbase+n*8+2*tq (+1)
        const long ra0 = r0 + m * 16 + gq;
        const long ra1 = ra0 + 8;
        const bool v0 = (ra0 < Mtotal), v1 = (ra1 < Mtotal);
#pragma unroll
        for (int n = 0; n < 4; n++) {
            const int col = colbase + n * 8 + 2 * tq;
            const float bb0 = b2s[col], bb1 = b2s[col + 1];
            if (v0) {
                float2 o; o.x = gelu_fast(acc[n][0] + bb0);
                          o.y = gelu_fast(acc[n][1] + bb1);
                *(float2*)(out + ra0 * NOUT + col) = o;
            }
            if (v1) {
                float2 o; o.x = gelu_fast(acc[n][2] + bb0);
                          o.y = gelu_fast(acc[n][3] + bb1);
                *(float2*)(out + ra1 * NOUT + col) = o;
            }
        }
    }
}

// ---------------------------------------------------------------------------
extern "C" void kernel_launch(void* const* d_in, const int* in_sizes, int n_in,
                              void* d_out, int out_size) {
    const float* x  = (const float*)d_in[0];
    const void*  ei = d_in[1];                    // int32 or int64 (2,E)
    const float* W1 = (const float*)d_in[2];
    const float* b1 = (const float*)d_in[3];
    const float* W2 = (const float*)d_in[4];
    const float* b2 = (const float*)d_in[5];
    float* out = (float*)d_out;

    const int E  = in_sizes[1] / 2;               // 300
    const int nG = in_sizes[0] / (NJ * DIN);      // 2048
    const int nTot = E + NJ;                      // 375
    const int Mtotal = nG * NJ;                   // 153600
    const int tiles = (Mtotal + 127) / 128;       // 1200

    cudaFuncSetAttribute(gemm_gelu, cudaFuncAttributeMaxDynamicSharedMemorySize,
                         SMB_TOTAL);

    setup_csr<<<1, 128>>>(ei, E, W2);
    gcn_partA<<<nG, 256>>>(x, W1, b1, nTot);
    gemm_gelu<<<tiles, 256, SMB_TOTAL>>>(b2, out, Mtotal);
}

// round 11
// speedup vs baseline: 2.3974x; 1.1450x over previous
#include <cuda_runtime.h>
#include <cuda_bf16.h>
#include <math.h>
#include <stdint.h>

// Problem constants: B=16,T=128 -> 2048 graphs; J=75; 3->64->256; E=300.
#define NJ    75
#define DIN   3
#define HID   64
#define NOUT  256
#define MAX_E 1024
#define MAX_T 544
#define MAXG  2048

// ---------------- persistent device scratch ----------------
__device__ int   g_csr_src[MAX_T];
__device__ float g_csr_w[MAX_T];
__device__ int   g_csr_off[NJ + 1];
__device__ __nv_bfloat16 g_ah_hi[MAXG * NJ * HID];   // ah1 split hi [row][k]
__device__ __nv_bfloat16 g_ah_lo[MAXG * NJ * HID];   // ah1 split lo
__device__ __nv_bfloat16 g_w2t_hi[NOUT * HID];       // W2^T split hi [n][k]
__device__ __nv_bfloat16 g_w2t_lo[NOUT * HID];       // W2^T split lo

// ---------------- math helpers ----------------
__device__ __forceinline__ float gelu_fast(float v) {
    const float x  = v * 0.70710678118654752f;
    const float ax = fabsf(x);
    const float den = fmaf(0.3275911f, ax, 1.0f);
    const float t   = __frcp_rn(den);
    float p = fmaf(1.061405429f, t, -1.453152027f);
    p = fmaf(p, t, 1.421413741f);
    p = fmaf(p, t, -0.284496736f);
    p = fmaf(p, t, 0.254829592f);
    p = p * t;
    const float ex   = __expf(-x * x);
    const float erfa = fmaf(-p, ex, 1.0f);
    return 0.5f * v * (1.0f + copysignf(erfa, x));
}
__device__ __forceinline__ int clampj(int v) {
    return v < 0 ? 0 : (v >= NJ ? NJ - 1 : v);
}

// Classic warp-level bf16 MMA (sm_80+ PTX, legal on plain sm_103 target).
#define MMA_BF16(d, a0, a1, a2, a3, b0, b1)                                   \
    asm volatile("mma.sync.aligned.m16n8k16.row.col.f32.bf16.bf16.f32 "       \
        "{%0,%1,%2,%3}, {%4,%5,%6,%7}, {%8,%9}, {%0,%1,%2,%3};"               \
        : "+f"((d)[0]), "+f"((d)[1]), "+f"((d)[2]), "+f"((d)[3])              \
        : "r"(a0), "r"(a1), "r"(a2), "r"(a3), "r"(b0), "r"(b1))

// ---------------------------------------------------------------------------
// Setup: CSR of normalized adjacency + W2^T bf16 hi/lo split. One block,
// fully parallelized (round-10 ncu: serial version cost 57us).
// ---------------------------------------------------------------------------
__global__ void __launch_bounds__(256)
setup_csr(const void* __restrict__ eiv, int E, const float* __restrict__ W2) {
    const int*       e32 = (const int*)eiv;
    const long long* e64 = (const long long*)eiv;

    __shared__ int   s_odd;
    __shared__ int   s_src[MAX_E];
    __shared__ int   s_dst[MAX_E];
    __shared__ int   s_deg[NJ];
    __shared__ float s_dis[NJ];
    __shared__ int   s_off[NJ + 1];

    const int t = threadIdx.x;

    // W2^T hi/lo split: iterate over OUTPUT index -> coalesced stores;
    // W2 reads are strided but L2/L1-resident (64KB).
    for (int i = t; i < NOUT * HID; i += blockDim.x) {
        int n = i >> 6, k = i & 63;
        float f = W2[k * NOUT + n];
        __nv_bfloat16 h = __float2bfloat16(f);
        __nv_bfloat16 l = __float2bfloat16(f - __bfloat162float(h));
        g_w2t_hi[i] = h;
        g_w2t_lo[i] = l;
    }

    // Parallel int64-vs-int32 detection (odd 32-bit words all zero <=> i64).
    if (t == 0) s_odd = 0;
    __syncthreads();
    {
        int local = 0;
        for (int i = 2 * t + 1; i < 2 * E; i += 2 * blockDim.x)
            local |= (e32[i] != 0);
        if (local) atomicOr(&s_odd, 1);
    }
    __syncthreads();
    const int is64 = !s_odd;

    for (int i = t; i < E; i += blockDim.x) {
        int sv, dv;
        if (is64) { sv = (int)e64[i]; dv = (int)e64[E + i]; }
        else      { sv = e32[i];      dv = e32[E + i]; }
        s_src[i] = clampj(sv);
        s_dst[i] = clampj(dv);
    }
    for (int j = t; j < NJ; j += blockDim.x) s_deg[j] = 1;  // self loop
    __syncthreads();
    for (int i = t; i < E; i += blockDim.x) atomicAdd(&s_deg[s_dst[i]], 1);
    __syncthreads();
    if (t == 0) {                       // 75-element prefix: trivial
        int acc = 0;
        for (int j = 0; j < NJ; j++) { s_off[j] = acc; acc += s_deg[j]; }
        s_off[NJ] = acc;
    }
    for (int j = t; j < NJ; j += blockDim.x) s_dis[j] = rsqrtf((float)s_deg[j]);
    __syncthreads();
    if (t < NJ) {
        int p = s_off[t];
        float dj = s_dis[t];
        for (int e = 0; e < E; e++) {
            if (s_dst[e] == t) {
                int se = s_src[e];
                g_csr_src[p] = se;
                g_csr_w[p]   = s_dis[se] * dj;
                p++;
            }
        }
        g_csr_src[p] = t;               // self loop last (reference order)
        g_csr_w[p]   = dj * dj;
    }
    for (int j = t; j <= NJ; j += blockDim.x) g_csr_off[j] = s_off[j];
}

// ---------------------------------------------------------------------------
// Part A (per-graph CTA): ah1 = A * gelu((A*x) W1 + b1), split to bf16 hi/lo.
// ---------------------------------------------------------------------------
__global__ void __launch_bounds__(256)
gcn_partA(const float* __restrict__ x,
          const float* __restrict__ W1, const float* __restrict__ b1,
          int nTot) {
    __shared__ __align__(16) float s_x  [NJ * DIN];
    __shared__ __align__(16) float s_ax [NJ * DIN];
    __shared__ __align__(16) float s_h1 [NJ * HID];
    __shared__ __align__(16) float s_ah1[NJ * HID];
    __shared__ __align__(16) float s_W1 [DIN * HID];
    __shared__ __align__(16) float s_b1 [HID];
    __shared__ int s_off[NJ + 1];
    __shared__ int s_src[MAX_T];
    __shared__ __align__(16) float s_w[MAX_T];

    const int t = threadIdx.x;
    const int g = blockIdx.x;

    const float* xg = x + (size_t)g * (NJ * DIN);
    for (int i = t; i < NJ * DIN; i += 256) s_x[i] = xg[i];
    for (int i = t; i < DIN * HID; i += 256) s_W1[i] = W1[i];
    if (t < HID) s_b1[t] = b1[t];
    for (int i = t; i <= NJ; i += 256) s_off[i] = g_csr_off[i];
    for (int i = t; i < nTot; i += 256) { s_src[i] = g_csr_src[i]; s_w[i] = g_csr_w[i]; }
    __syncthreads();

    // phase 1: ax = A * x
    for (int idx = t; idx < NJ * DIN; idx += 256) {
        int j = idx / DIN, d = idx - j * DIN;
        float acc = 0.f;
        int e0 = s_off[j], e1 = s_off[j + 1];
        for (int e = e0; e < e1; e++) acc += s_w[e] * s_x[s_src[e] * DIN + d];
        s_ax[idx] = acc;
    }
    __syncthreads();

    // phase 2: h1 = gelu(ax @ W1 + b1)
    for (int idx = t; idx < NJ * HID; idx += 256) {
        int j = idx >> 6, k = idx & 63;
        float v = fmaf(s_ax[j * DIN + 0], s_W1[k],
                  fmaf(s_ax[j * DIN + 1], s_W1[HID + k],
                  fmaf(s_ax[j * DIN + 2], s_W1[2 * HID + k], s_b1[k])));
        s_h1[idx] = gelu_fast(v);
    }
    __syncthreads();

    // phase 3: ah1 = A * h1
    for (int idx = t; idx < NJ * HID; idx += 256) {
        int j = idx >> 6, k = idx & 63;
        float acc = 0.f;
        int e0 = s_off[j], e1 = s_off[j + 1];
        for (int e = e0; e < e1; e++) acc += s_w[e] * s_h1[(s_src[e] << 6) + k];
        s_ah1[idx] = acc;
    }
    __syncthreads();

    // split to bf16 hi/lo, coalesced store
    const size_t base = (size_t)g * (NJ * HID);
    for (int i = t; i < NJ * HID; i += 256) {
        float f = s_ah1[i];
        __nv_bfloat16 h = __float2bfloat16(f);
        __nv_bfloat16 l = __float2bfloat16(f - __bfloat162float(h));
        g_ah_hi[base + i] = h;
        g_ah_lo[base + i] = l;
    }
}

// ---------------------------------------------------------------------------
// Part B: out = gelu(AH1[Mtotal,64] @ W2[64,256] + b2) via warp-level
// bf16 mma.sync with 3-term hi/lo compensation. 128-row M tiles.
// SMEM u32 rows at stride 36 -> conflict-free fragment gathers.
// ---------------------------------------------------------------------------
#define STRD 36
#define SM_AHI 0
#define SM_ALO (SM_AHI + 128 * STRD * 4)
#define SM_BHI (SM_ALO + 128 * STRD * 4)
#define SM_BLO (SM_BHI + 256 * STRD * 4)
#define SM_B2  (SM_BLO + 256 * STRD * 4)
#define SMB_TOTAL (SM_B2 + NOUT * 4)

__global__ void __launch_bounds__(256)
gemm_gelu(const float* __restrict__ b2, float* __restrict__ out, int Mtotal) {
    extern __shared__ __align__(16) char smem[];
    uint32_t* sAh = (uint32_t*)(smem + SM_AHI);
    uint32_t* sAl = (uint32_t*)(smem + SM_ALO);
    uint32_t* sBh = (uint32_t*)(smem + SM_BHI);
    uint32_t* sBl = (uint32_t*)(smem + SM_BLO);
    float*    b2s = (float*)(smem + SM_B2);

    const int t   = threadIdx.x;
    const int wid = t >> 5;
    const int lid = t & 31;
    const int gq  = lid >> 2;
    const int tq  = lid & 3;
    const long r0 = (long)blockIdx.x * 128;

    for (int i = t; i < 128 * 32; i += 256) {
        int row = i >> 5, p = i & 31;
        long r = r0 + row; if (r >= Mtotal) r = Mtotal - 1;
        sAh[row * STRD + p] = ((const uint32_t*)g_ah_hi)[r * 32 + p];
        sAl[row * STRD + p] = ((const uint32_t*)g_ah_lo)[r * 32 + p];
    }
    for (int i = t; i < 256 * 32; i += 256) {
        int row = i >> 5, p = i & 31;
        sBh[row * STRD + p] = ((const uint32_t*)g_w2t_hi)[row * 32 + p];
        sBl[row * STRD + p] = ((const uint32_t*)g_w2t_lo)[row * 32 + p];
    }
    if (t < NOUT) b2s[t] = b2[t];
    __syncthreads();

    const int colbase = wid * 32;
    for (int m = 0; m < 8; m++) {
        float acc[4][4];
#pragma unroll
        for (int n = 0; n < 4; n++) { acc[n][0] = acc[n][1] = acc[n][2] = acc[n][3] = 0.f; }

#pragma unroll
        for (int q = 0; q < 4; q++) {
            const int ra = (m * 16 + gq) * STRD + q * 8 + tq;
            const uint32_t ah0 = sAh[ra],     ah1 = sAh[ra + 8 * STRD];
            const uint32_t ah2 = sAh[ra + 4], ah3 = sAh[ra + 8 * STRD + 4];
            const uint32_t al0 = sAl[ra],     al1 = sAl[ra + 8 * STRD];
            const uint32_t al2 = sAl[ra + 4], al3 = sAl[ra + 8 * STRD + 4];
#pragma unroll
            for (int n = 0; n < 4; n++) {
                const int rb = (colbase + n * 8 + gq) * STRD + q * 8 + tq;
                const uint32_t bh0 = sBh[rb], bh1 = sBh[rb + 4];
                const uint32_t bl0 = sBl[rb], bl1 = sBl[rb + 4];
                MMA_BF16(acc[n], ah0, ah1, ah2, ah3, bh0, bh1);
                MMA_BF16(acc[n], al0, al1, al2, al3, bh0, bh1);
                MMA_BF16(acc[n], ah0, ah1, ah2, ah3, bl0, bl1);
            }
        }

        const long ra0 = r0 + m * 16 + gq;
        const long ra1 = ra0 + 8;
        const bool v0 = (ra0 < Mtotal), v1 = (ra1 < Mtotal);
#pragma unroll
        for (int n = 0; n < 4; n++) {
            const int col = colbase + n * 8 + 2 * tq;
            const float bb0 = b2s[col], bb1 = b2s[col + 1];
            if (v0) {
                float2 o; o.x = gelu_fast(acc[n][0] + bb0);
                          o.y = gelu_fast(acc[n][1] + bb1);
                *(float2*)(out + ra0 * NOUT + col) = o;
            }
            if (v1) {
                float2 o; o.x = gelu_fast(acc[n][2] + bb0);
                          o.y = gelu_fast(acc[n][3] + bb1);
                *(float2*)(out + ra1 * NOUT + col) = o;
            }
        }
    }
}

// ---------------------------------------------------------------------------
extern "C" void kernel_launch(void* const* d_in, const int* in_sizes, int n_in,
                              void* d_out, int out_size) {
    const float* x  = (const float*)d_in[0];
    const void*  ei = d_in[1];                    // int32 or int64 (2,E)
    const float* W1 = (const float*)d_in[2];
    const float* b1 = (const float*)d_in[3];
    const float* W2 = (const float*)d_in[4];
    const float* b2 = (const float*)d_in[5];
    float* out = (float*)d_out;

    const int E  = in_sizes[1] / 2;               // 300
    const int nG = in_sizes[0] / (NJ * DIN);      // 2048
    const int nTot = E + NJ;                      // 375
    const int Mtotal = nG * NJ;                   // 153600
    const int tiles = (Mtotal + 127) / 128;       // 1200

    cudaFuncSetAttribute(gemm_gelu, cudaFuncAttributeMaxDynamicSharedMemorySize,
                         SMB_TOTAL);

    setup_csr<<<1, 256>>>(ei, E, W2);
    gcn_partA<<<nG, 256>>>(x, W1, b1, nTot);
    gemm_gelu<<<tiles, 256, SMB_TOTAL>>>(b2, out, Mtotal);
}